// round 1
// baseline (speedup 1.0000x reference)
#include <cuda_runtime.h>
#include <math.h>
#include <cstdint>

#define B_ 4
#define S_ 2048
#define D_ 1024
#define H_ 16
#define DK_ 64

// Scratch: device globals (no allocation allowed anywhere)
__device__ float g_Q[(size_t)B_ * S_ * D_];
__device__ float g_K[(size_t)B_ * S_ * D_];
__device__ float g_V[(size_t)B_ * S_ * D_];
__device__ float g_att[(size_t)B_ * S_ * D_];

// ---------------------------------------------------------------------------
// C[M,N] = A[M,K] @ B[N,K]^T + bias[N]   (torch Linear: y = x @ W.T + b)
// 64x64 block tile, BK=16, 256 threads, 4x4 microtile per thread.
// ---------------------------------------------------------------------------
__global__ void __launch_bounds__(256) gemm_nt_bias(
    const float* __restrict__ A, const float* __restrict__ Bm,
    const float* __restrict__ bias, float* __restrict__ C,
    int M, int N, int K)
{
    __shared__ float As[16][68];  // [k][m]
    __shared__ float Bs[16][68];  // [k][n]

    const int tid = threadIdx.x;
    const int tx = tid & 15, ty = tid >> 4;
    const int r0 = ty * 4, c0 = tx * 4;
    const int m0 = blockIdx.y * 64, n0 = blockIdx.x * 64;

    const int lr = tid >> 2;        // 0..63 (row within tile)
    const int lk = (tid & 3) * 4;   // 0,4,8,12 (k offset)

    const float* Ap = A + (size_t)(m0 + lr) * K + lk;
    const float* Bp = Bm + (size_t)(n0 + lr) * K + lk;

    float acc[4][4] = {};

    for (int k0 = 0; k0 < K; k0 += 16) {
        float4 av = *(const float4*)(Ap + k0);
        float4 bv = *(const float4*)(Bp + k0);
        __syncthreads();
        As[lk + 0][lr] = av.x; As[lk + 1][lr] = av.y;
        As[lk + 2][lr] = av.z; As[lk + 3][lr] = av.w;
        Bs[lk + 0][lr] = bv.x; Bs[lk + 1][lr] = bv.y;
        Bs[lk + 2][lr] = bv.z; Bs[lk + 3][lr] = bv.w;
        __syncthreads();
#pragma unroll
        for (int kk = 0; kk < 16; kk++) {
            float4 a = *(const float4*)&As[kk][r0];
            float4 b = *(const float4*)&Bs[kk][c0];
            float aa[4] = {a.x, a.y, a.z, a.w};
            float bb[4] = {b.x, b.y, b.z, b.w};
#pragma unroll
            for (int i = 0; i < 4; i++)
#pragma unroll
                for (int j = 0; j < 4; j++)
                    acc[i][j] = fmaf(aa[i], bb[j], acc[i][j]);
        }
    }

#pragma unroll
    for (int i = 0; i < 4; i++) {
#pragma unroll
        for (int j = 0; j < 4; j++) {
            C[(size_t)(m0 + r0 + i) * N + n0 + c0 + j] =
                acc[i][j] + bias[n0 + c0 + j];
        }
    }
}

// ---------------------------------------------------------------------------
// Flash-attention (fp32, causal). One block per (q-tile of 64 rows, head, batch).
// Q/K/V layouts are [B,S,D] with head h occupying columns [h*64, h*64+64).
// Online softmax with 64-key tiles. 256 threads, 4x4 microtiles.
// ---------------------------------------------------------------------------
__global__ void __launch_bounds__(256) attn_kernel(
    const float* __restrict__ Qg, const float* __restrict__ Kg,
    const float* __restrict__ Vg, float* __restrict__ Og)
{
    extern __shared__ float sm[];
    float* Qt = sm;                // [d][r]  stride 68
    float* Kt = Qt + 64 * 68;      // [d][c]  stride 68
    float* Vs = Kt + 64 * 68;      // [k][d]  stride 68
    float* Ps = Vs + 64 * 68;      // [r][k]  stride 65

    const int qt = blockIdx.x, h = blockIdx.y, b = blockIdx.z;
    const int tid = threadIdx.x;
    const int tx = tid & 15, ty = tid >> 4;
    const int r0 = ty * 4, c0 = tx * 4;
    const int q0 = qt * 64;

    const float* Qb = Qg + (size_t)b * S_ * D_ + h * DK_;
    const float* Kb = Kg + (size_t)b * S_ * D_ + h * DK_;
    const float* Vb = Vg + (size_t)b * S_ * D_ + h * DK_;

    // Load Q tile transposed [d][r]
    for (int idx = tid; idx < 64 * 64; idx += 256) {
        int r = idx >> 6, d = idx & 63;
        Qt[d * 68 + r] = Qb[(size_t)(q0 + r) * D_ + d];
    }

    const float NEG = -1e30f;
    float m_i[4], l_i[4], o[4][4];
#pragma unroll
    for (int i = 0; i < 4; i++) {
        m_i[i] = NEG; l_i[i] = 0.f;
#pragma unroll
        for (int j = 0; j < 4; j++) o[i][j] = 0.f;
    }
    __syncthreads();

    for (int kb = 0; kb <= qt; kb++) {
        const int k0 = kb * 64;
        // Load K (transposed) and V (natural) tiles
        for (int idx = tid; idx < 64 * 64; idx += 256) {
            int c = idx >> 6, d = idx & 63;
            size_t go = (size_t)(k0 + c) * D_ + d;
            Kt[d * 68 + c] = Kb[go];
            Vs[c * 68 + d] = Vb[go];
        }
        __syncthreads();

        // S = Q @ K^T  (over d)
        float s[4][4] = {};
#pragma unroll
        for (int kk = 0; kk < 64; kk++) {
            float4 a = *(const float4*)&Qt[kk * 68 + r0];
            float4 bq = *(const float4*)&Kt[kk * 68 + c0];
            float aa[4] = {a.x, a.y, a.z, a.w};
            float bb[4] = {bq.x, bq.y, bq.z, bq.w};
#pragma unroll
            for (int i = 0; i < 4; i++)
#pragma unroll
                for (int j = 0; j < 4; j++)
                    s[i][j] = fmaf(aa[i], bb[j], s[i][j]);
        }

        const float scale = 0.125f;  // 1/sqrt(64)
#pragma unroll
        for (int i = 0; i < 4; i++)
#pragma unroll
            for (int j = 0; j < 4; j++) s[i][j] *= scale;

        if (kb == qt) {
            // diagonal tile: mask key > query (tile-local offsets share base)
#pragma unroll
            for (int i = 0; i < 4; i++)
#pragma unroll
                for (int j = 0; j < 4; j++)
                    if (c0 + j > r0 + i) s[i][j] = NEG;
        }

        // online softmax per row (reduce over 16 tx lanes)
#pragma unroll
        for (int i = 0; i < 4; i++) {
            float mx = fmaxf(fmaxf(s[i][0], s[i][1]), fmaxf(s[i][2], s[i][3]));
#pragma unroll
            for (int off = 1; off < 16; off <<= 1)
                mx = fmaxf(mx, __shfl_xor_sync(0xffffffffu, mx, off));
            float mnew = fmaxf(m_i[i], mx);
            float alpha = __expf(m_i[i] - mnew);
            m_i[i] = mnew;
            float rs = 0.f;
#pragma unroll
            for (int j = 0; j < 4; j++) {
                float p = __expf(s[i][j] - mnew);
                s[i][j] = p;
                rs += p;
            }
#pragma unroll
            for (int off = 1; off < 16; off <<= 1)
                rs += __shfl_xor_sync(0xffffffffu, rs, off);
            l_i[i] = l_i[i] * alpha + rs;
#pragma unroll
            for (int j = 0; j < 4; j++) o[i][j] *= alpha;
        }

        // write P
#pragma unroll
        for (int i = 0; i < 4; i++)
#pragma unroll
            for (int j = 0; j < 4; j++)
                Ps[(r0 + i) * 65 + c0 + j] = s[i][j];
        __syncthreads();

        // O += P @ V  (over keys)
#pragma unroll
        for (int kk = 0; kk < 64; kk++) {
            float4 vv = *(const float4*)&Vs[kk * 68 + c0];
            float vb[4] = {vv.x, vv.y, vv.z, vv.w};
            float pa[4];
#pragma unroll
            for (int i = 0; i < 4; i++) pa[i] = Ps[(r0 + i) * 65 + kk];
#pragma unroll
            for (int i = 0; i < 4; i++)
#pragma unroll
                for (int j = 0; j < 4; j++)
                    o[i][j] = fmaf(pa[i], vb[j], o[i][j]);
        }
        __syncthreads();
    }

    float* Ob = Og + (size_t)b * S_ * D_ + h * DK_;
#pragma unroll
    for (int i = 0; i < 4; i++) {
        float inv = 1.f / l_i[i];
#pragma unroll
        for (int j = 0; j < 4; j++)
            Ob[(size_t)(q0 + r0 + i) * D_ + c0 + j] = o[i][j] * inv;
    }
}

// ---------------------------------------------------------------------------
extern "C" void kernel_launch(void* const* d_in, const int* in_sizes, int n_in,
                              void* d_out, int out_size)
{
    const float* q  = (const float*)d_in[0];
    const float* k  = (const float*)d_in[1];
    const float* v  = (const float*)d_in[2];
    const float* Wq = (const float*)d_in[3];
    const float* bq = (const float*)d_in[4];
    const float* Wk = (const float*)d_in[5];
    const float* bk = (const float*)d_in[6];
    const float* Wv = (const float*)d_in[7];
    const float* bv = (const float*)d_in[8];
    const float* Wo = (const float*)d_in[9];
    const float* bo = (const float*)d_in[10];
    // d_in[11] = causal mask (computed analytically, unused)
    float* out = (float*)d_out;

    float *pQ, *pK, *pV, *pA;
    cudaGetSymbolAddress((void**)&pQ, g_Q);
    cudaGetSymbolAddress((void**)&pK, g_K);
    cudaGetSymbolAddress((void**)&pV, g_V);
    cudaGetSymbolAddress((void**)&pA, g_att);

    const int M = B_ * S_;   // 8192
    dim3 blk(256);
    dim3 gproj(D_ / 64, M / 64);   // (16, 128)

    gemm_nt_bias<<<gproj, blk>>>(q, Wq, bq, pQ, M, D_, D_);
    gemm_nt_bias<<<gproj, blk>>>(k, Wk, bk, pK, M, D_, D_);
    gemm_nt_bias<<<gproj, blk>>>(v, Wv, bv, pV, M, D_, D_);

    const int smem_bytes = (3 * 64 * 68 + 64 * 65) * (int)sizeof(float);  // 68864
    cudaFuncSetAttribute(attn_kernel,
                         cudaFuncAttributeMaxDynamicSharedMemorySize, smem_bytes);
    dim3 gatt(S_ / 64, H_, B_);
    attn_kernel<<<gatt, blk, smem_bytes>>>(pQ, pK, pV, pA);

    gemm_nt_bias<<<gproj, blk>>>(pA, Wo, bo, out, M, D_, D_);
}

// round 2
// speedup vs baseline: 5.6083x; 5.6083x over previous
#include <cuda_runtime.h>
#include <math.h>
#include <cstdint>

#define B_ 4
#define S_ 2048
#define D_ 1024
#define H_ 16
#define DK_ 64

// Scratch: device globals (no allocation allowed anywhere)
__device__ float g_Q[(size_t)B_ * S_ * D_];
__device__ float g_K[(size_t)B_ * S_ * D_];
__device__ float g_V[(size_t)B_ * S_ * D_];
__device__ float g_att[(size_t)B_ * S_ * D_];

__device__ __forceinline__ uint32_t f2tf32(float f) {
    uint32_t u;
    asm("cvt.rna.tf32.f32 %0, %1;" : "=r"(u) : "f"(f));
    return u;
}

__device__ __forceinline__ void mma_tf32(float* d, const uint32_t* a, const uint32_t* b) {
    asm volatile(
        "mma.sync.aligned.m16n8k8.row.col.f32.tf32.tf32.f32 "
        "{%0,%1,%2,%3}, {%4,%5,%6,%7}, {%8,%9}, {%0,%1,%2,%3};\n"
        : "+f"(d[0]), "+f"(d[1]), "+f"(d[2]), "+f"(d[3])
        : "r"(a[0]), "r"(a[1]), "r"(a[2]), "r"(a[3]), "r"(b[0]), "r"(b[1]));
}

__device__ __forceinline__ uint32_t s2u(const void* p) {
    return (uint32_t)__cvta_generic_to_shared(p);
}
#define CP_ASYNC16(smem, gmem) \
    asm volatile("cp.async.cg.shared.global [%0], [%1], 16;\n" :: "r"(smem), "l"(gmem))
#define CP_COMMIT() asm volatile("cp.async.commit_group;\n")
#define CP_WAIT(n)  asm volatile("cp.async.wait_group %0;\n" :: "n"(n))

// ---------------------------------------------------------------------------
// C[M,N] = A[M,K] @ B[N,K]^T + bias[N]  via tf32 mma.sync
// 128x128x32 tile, 256 threads (8 warps, 4x2), each warp 32x64.
// ---------------------------------------------------------------------------
__global__ void __launch_bounds__(256) gemm_tf32(
    const float* __restrict__ A, const float* __restrict__ Bm,
    const float* __restrict__ bias, float* __restrict__ C,
    int M, int N, int K)
{
    extern __shared__ float sm[];
    float (*As)[128][36] = (float(*)[128][36])sm;               // [2][128][36]
    float (*Bs)[128][36] = (float(*)[128][36])(sm + 2 * 128 * 36);

    const int tid = threadIdx.x;
    const int lane = tid & 31, warp = tid >> 5;
    const int wr = warp >> 1, wc = warp & 1;
    const int m0 = blockIdx.y * 128, n0 = blockIdx.x * 128;
    const int l4 = lane >> 2, lm = lane & 3;

    const int cr = tid >> 3;          // 0..31
    const int cc = (tid & 7) * 4;     // 0..28

    const float* Ap = A + (size_t)(m0 + cr) * K + cc;
    const float* Bp = Bm + (size_t)(n0 + cr) * K + cc;

    float acc[2][8][4];
#pragma unroll
    for (int i = 0; i < 2; i++)
#pragma unroll
        for (int j = 0; j < 8; j++)
#pragma unroll
            for (int t = 0; t < 4; t++) acc[i][j][t] = 0.f;

    const int nk = K >> 5;

    // prologue: stage tile 0
    {
#pragma unroll
        for (int i = 0; i < 4; i++) {
            CP_ASYNC16(s2u(&As[0][cr + 32 * i][cc]), Ap + (size_t)(32 * i) * K);
            CP_ASYNC16(s2u(&Bs[0][cr + 32 * i][cc]), Bp + (size_t)(32 * i) * K);
        }
        CP_COMMIT();
    }

    for (int kt = 0; kt < nk; kt++) {
        const int buf = kt & 1;
        if (kt + 1 < nk) {
            const int nb = buf ^ 1;
            const int ko = (kt + 1) * 32;
#pragma unroll
            for (int i = 0; i < 4; i++) {
                CP_ASYNC16(s2u(&As[nb][cr + 32 * i][cc]), Ap + (size_t)(32 * i) * K + ko);
                CP_ASYNC16(s2u(&Bs[nb][cr + 32 * i][cc]), Bp + (size_t)(32 * i) * K + ko);
            }
            CP_COMMIT();
            CP_WAIT(1);
        } else {
            CP_WAIT(0);
        }
        __syncthreads();

#pragma unroll
        for (int ks = 0; ks < 4; ks++) {
            const int kc = ks * 8 + lm;
            uint32_t af[2][4], bf[8][2];
#pragma unroll
            for (int mt = 0; mt < 2; mt++) {
                const int r = wr * 32 + mt * 16 + l4;
                af[mt][0] = f2tf32(As[buf][r][kc]);
                af[mt][1] = f2tf32(As[buf][r + 8][kc]);
                af[mt][2] = f2tf32(As[buf][r][kc + 4]);
                af[mt][3] = f2tf32(As[buf][r + 8][kc + 4]);
            }
#pragma unroll
            for (int nt = 0; nt < 8; nt++) {
                const int c = wc * 64 + nt * 8 + l4;
                bf[nt][0] = f2tf32(Bs[buf][c][kc]);
                bf[nt][1] = f2tf32(Bs[buf][c][kc + 4]);
            }
#pragma unroll
            for (int mt = 0; mt < 2; mt++)
#pragma unroll
                for (int nt = 0; nt < 8; nt++)
                    mma_tf32(acc[mt][nt], af[mt], bf[nt]);
        }
        __syncthreads();
    }

    // epilogue with bias
#pragma unroll
    for (int mt = 0; mt < 2; mt++) {
        const int r = m0 + wr * 32 + mt * 16 + l4;
#pragma unroll
        for (int nt = 0; nt < 8; nt++) {
            const int c = n0 + wc * 64 + nt * 8 + 2 * lm;
            const float2 b2 = *(const float2*)&bias[c];
            float2 v0 = {acc[mt][nt][0] + b2.x, acc[mt][nt][1] + b2.y};
            float2 v1 = {acc[mt][nt][2] + b2.x, acc[mt][nt][3] + b2.y};
            *(float2*)&C[(size_t)r * N + c] = v0;
            *(float2*)&C[(size_t)(r + 8) * N + c] = v1;
        }
    }
}

// ---------------------------------------------------------------------------
// Flash attention, tf32 mma.sync. CTA = 128 q-rows, 256 threads (8 warps x 16
// rows). 64-key tiles. Q fragments live in registers for the whole kernel.
// ---------------------------------------------------------------------------
__global__ void __launch_bounds__(256) attn_tf32(
    const float* __restrict__ Qg, const float* __restrict__ Kg,
    const float* __restrict__ Vg, float* __restrict__ Og)
{
    extern __shared__ float sm[];
    float* QP = sm;                 // [128][68] : Q staging, then P (per-warp rows)
    float* Ks = QP + 128 * 68;      // [64][68]
    float* Vs = Ks + 64 * 68;       // [64][72]

    const int qt = blockIdx.x, h = blockIdx.y, b = blockIdx.z;
    const int tid = threadIdx.x, lane = tid & 31, warp = tid >> 5;
    const int l4 = lane >> 2, lm = lane & 3;
    const int q0 = qt * 128;

    const float* Qb = Qg + (size_t)b * S_ * D_ + h * DK_;
    const float* Kb = Kg + (size_t)b * S_ * D_ + h * DK_;
    const float* Vb = Vg + (size_t)b * S_ * D_ + h * DK_;

    // Load Q tile (convert to tf32 bits)
    {
        const int rr = tid >> 4, c4 = (tid & 15) * 4;
#pragma unroll
        for (int j = 0; j < 8; j++) {
            const int r = rr + j * 16;
            const float4 v = *(const float4*)&Qb[(size_t)(q0 + r) * D_ + c4];
            QP[r * 68 + c4 + 0] = __uint_as_float(f2tf32(v.x));
            QP[r * 68 + c4 + 1] = __uint_as_float(f2tf32(v.y));
            QP[r * 68 + c4 + 2] = __uint_as_float(f2tf32(v.z));
            QP[r * 68 + c4 + 3] = __uint_as_float(f2tf32(v.w));
        }
    }
    __syncthreads();

    // Extract Q fragments (warp reads only its own 16 rows)
    uint32_t qf[8][4];
    {
        const int r = warp * 16 + l4;
#pragma unroll
        for (int ks = 0; ks < 8; ks++) {
            const int c = ks * 8 + lm;
            qf[ks][0] = __float_as_uint(QP[r * 68 + c]);
            qf[ks][1] = __float_as_uint(QP[(r + 8) * 68 + c]);
            qf[ks][2] = __float_as_uint(QP[r * 68 + c + 4]);
            qf[ks][3] = __float_as_uint(QP[(r + 8) * 68 + c + 4]);
        }
    }

    float m0r = -1e30f, m1r = -1e30f, l0r = 0.f, l1r = 0.f;
    float o[8][4];
#pragma unroll
    for (int nt = 0; nt < 8; nt++)
#pragma unroll
        for (int i = 0; i < 4; i++) o[nt][i] = 0.f;

    float* Pw = QP + warp * 16 * 68;
    const int qr_lo = q0 + warp * 16;
    const int qr_hi = qr_lo + 15;
    const int nkb = 2 * qt + 2;

    for (int kb = 0; kb < nkb; kb++) {
        const int k0 = kb * 64;
        __syncthreads();
        // Cooperative K,V tile load (tf32)
        {
            const int rr = tid >> 4, c4 = (tid & 15) * 4;
#pragma unroll
            for (int j = 0; j < 4; j++) {
                const int r = rr + j * 16;
                const size_t go = (size_t)(k0 + r) * D_ + c4;
                const float4 kv = *(const float4*)&Kb[go];
                const float4 vv = *(const float4*)&Vb[go];
                Ks[r * 68 + c4 + 0] = __uint_as_float(f2tf32(kv.x));
                Ks[r * 68 + c4 + 1] = __uint_as_float(f2tf32(kv.y));
                Ks[r * 68 + c4 + 2] = __uint_as_float(f2tf32(kv.z));
                Ks[r * 68 + c4 + 3] = __uint_as_float(f2tf32(kv.w));
                Vs[r * 72 + c4 + 0] = __uint_as_float(f2tf32(vv.x));
                Vs[r * 72 + c4 + 1] = __uint_as_float(f2tf32(vv.y));
                Vs[r * 72 + c4 + 2] = __uint_as_float(f2tf32(vv.z));
                Vs[r * 72 + c4 + 3] = __uint_as_float(f2tf32(vv.w));
            }
        }
        __syncthreads();
        if (k0 > qr_hi) continue;   // whole tile masked for this warp (uniform)

        // S = Q @ K^T
        float s[8][4];
#pragma unroll
        for (int nt = 0; nt < 8; nt++)
#pragma unroll
            for (int i = 0; i < 4; i++) s[nt][i] = 0.f;
#pragma unroll
        for (int ks = 0; ks < 8; ks++) {
            const int kc = ks * 8 + lm;
#pragma unroll
            for (int nt = 0; nt < 8; nt++) {
                uint32_t bb[2] = {
                    __float_as_uint(Ks[(nt * 8 + l4) * 68 + kc]),
                    __float_as_uint(Ks[(nt * 8 + l4) * 68 + kc + 4])
                };
                mma_tf32(s[nt], qf[ks], bb);
            }
        }

        // scale + causal mask
        const bool full = (k0 + 63) <= qr_lo;
        const int r0g = qr_lo + l4, r1g = r0g + 8;
#pragma unroll
        for (int nt = 0; nt < 8; nt++) {
#pragma unroll
            for (int i = 0; i < 4; i++) s[nt][i] *= 0.125f;
            if (!full) {
                const int c = k0 + nt * 8 + 2 * lm;
                if (c     > r0g) s[nt][0] = -1e30f;
                if (c + 1 > r0g) s[nt][1] = -1e30f;
                if (c     > r1g) s[nt][2] = -1e30f;
                if (c + 1 > r1g) s[nt][3] = -1e30f;
            }
        }

        // online softmax (rows r0g: regs 0,1 / r1g: regs 2,3); quad reduction
        float mx0 = -1e30f, mx1 = -1e30f;
#pragma unroll
        for (int nt = 0; nt < 8; nt++) {
            mx0 = fmaxf(mx0, fmaxf(s[nt][0], s[nt][1]));
            mx1 = fmaxf(mx1, fmaxf(s[nt][2], s[nt][3]));
        }
        mx0 = fmaxf(mx0, __shfl_xor_sync(0xffffffffu, mx0, 1));
        mx0 = fmaxf(mx0, __shfl_xor_sync(0xffffffffu, mx0, 2));
        mx1 = fmaxf(mx1, __shfl_xor_sync(0xffffffffu, mx1, 1));
        mx1 = fmaxf(mx1, __shfl_xor_sync(0xffffffffu, mx1, 2));
        const float mn0 = fmaxf(m0r, mx0), mn1 = fmaxf(m1r, mx1);
        const float a0 = __expf(m0r - mn0), a1 = __expf(m1r - mn1);
        m0r = mn0; m1r = mn1;
        float sum0 = 0.f, sum1 = 0.f;
#pragma unroll
        for (int nt = 0; nt < 8; nt++) {
            s[nt][0] = __expf(s[nt][0] - mn0); sum0 += s[nt][0];
            s[nt][1] = __expf(s[nt][1] - mn0); sum0 += s[nt][1];
            s[nt][2] = __expf(s[nt][2] - mn1); sum1 += s[nt][2];
            s[nt][3] = __expf(s[nt][3] - mn1); sum1 += s[nt][3];
        }
        sum0 += __shfl_xor_sync(0xffffffffu, sum0, 1);
        sum0 += __shfl_xor_sync(0xffffffffu, sum0, 2);
        sum1 += __shfl_xor_sync(0xffffffffu, sum1, 1);
        sum1 += __shfl_xor_sync(0xffffffffu, sum1, 2);
        l0r = l0r * a0 + sum0;
        l1r = l1r * a1 + sum1;
#pragma unroll
        for (int nt = 0; nt < 8; nt++) {
            o[nt][0] *= a0; o[nt][1] *= a0;
            o[nt][2] *= a1; o[nt][3] *= a1;
        }

        // store P (tf32) into per-warp region
#pragma unroll
        for (int nt = 0; nt < 8; nt++) {
            const int c = nt * 8 + 2 * lm;
            float2 p0 = {__uint_as_float(f2tf32(s[nt][0])), __uint_as_float(f2tf32(s[nt][1]))};
            float2 p1 = {__uint_as_float(f2tf32(s[nt][2])), __uint_as_float(f2tf32(s[nt][3]))};
            *(float2*)&Pw[l4 * 68 + c]       = p0;
            *(float2*)&Pw[(l4 + 8) * 68 + c] = p1;
        }
        __syncwarp();

        // O += P @ V
#pragma unroll
        for (int ks = 0; ks < 8; ks++) {
            const int kc = ks * 8 + lm;
            uint32_t pa[4];
            pa[0] = __float_as_uint(Pw[l4 * 68 + kc]);
            pa[1] = __float_as_uint(Pw[(l4 + 8) * 68 + kc]);
            pa[2] = __float_as_uint(Pw[l4 * 68 + kc + 4]);
            pa[3] = __float_as_uint(Pw[(l4 + 8) * 68 + kc + 4]);
#pragma unroll
            for (int nt = 0; nt < 8; nt++) {
                uint32_t bb[2] = {
                    __float_as_uint(Vs[(ks * 8 + lm) * 72 + nt * 8 + l4]),
                    __float_as_uint(Vs[(ks * 8 + lm + 4) * 72 + nt * 8 + l4])
                };
                mma_tf32(o[nt], pa, bb);
            }
        }
    }

    // epilogue: normalize and store
    const float inv0 = 1.f / l0r, inv1 = 1.f / l1r;
    float* Ob = Og + (size_t)b * S_ * D_ + h * DK_;
    const int r0g = q0 + warp * 16 + l4, r1g = r0g + 8;
#pragma unroll
    for (int nt = 0; nt < 8; nt++) {
        const int c = nt * 8 + 2 * lm;
        float2 v0 = {o[nt][0] * inv0, o[nt][1] * inv0};
        float2 v1 = {o[nt][2] * inv1, o[nt][3] * inv1};
        *(float2*)&Ob[(size_t)r0g * D_ + c] = v0;
        *(float2*)&Ob[(size_t)r1g * D_ + c] = v1;
    }
}

// ---------------------------------------------------------------------------
extern "C" void kernel_launch(void* const* d_in, const int* in_sizes, int n_in,
                              void* d_out, int out_size)
{
    const float* q  = (const float*)d_in[0];
    const float* k  = (const float*)d_in[1];
    const float* v  = (const float*)d_in[2];
    const float* Wq = (const float*)d_in[3];
    const float* bq = (const float*)d_in[4];
    const float* Wk = (const float*)d_in[5];
    const float* bk = (const float*)d_in[6];
    const float* Wv = (const float*)d_in[7];
    const float* bv = (const float*)d_in[8];
    const float* Wo = (const float*)d_in[9];
    const float* bo = (const float*)d_in[10];
    // d_in[11] = causal mask (computed analytically, unused)
    float* out = (float*)d_out;

    float *pQ, *pK, *pV, *pA;
    cudaGetSymbolAddress((void**)&pQ, g_Q);
    cudaGetSymbolAddress((void**)&pK, g_K);
    cudaGetSymbolAddress((void**)&pV, g_V);
    cudaGetSymbolAddress((void**)&pA, g_att);

    const int M = B_ * S_;  // 8192
    const int gemm_smem = 2 * 128 * 36 * 2 * (int)sizeof(float);  // 73728
    const int attn_smem = (128 * 68 + 64 * 68 + 64 * 72) * (int)sizeof(float);  // 70656

    cudaFuncSetAttribute(gemm_tf32, cudaFuncAttributeMaxDynamicSharedMemorySize, gemm_smem);
    cudaFuncSetAttribute(attn_tf32, cudaFuncAttributeMaxDynamicSharedMemorySize, attn_smem);

    dim3 blk(256);
    dim3 gproj(D_ / 128, M / 128);  // (8, 64)

    gemm_tf32<<<gproj, blk, gemm_smem>>>(q, Wq, bq, pQ, M, D_, D_);
    gemm_tf32<<<gproj, blk, gemm_smem>>>(k, Wk, bk, pK, M, D_, D_);
    gemm_tf32<<<gproj, blk, gemm_smem>>>(v, Wv, bv, pV, M, D_, D_);

    dim3 gatt(S_ / 128, H_, B_);
    attn_tf32<<<gatt, blk, attn_smem>>>(pQ, pK, pV, pA);

    gemm_tf32<<<gproj, blk, gemm_smem>>>(pA, Wo, bo, out, M, D_, D_);
}

// round 3
// speedup vs baseline: 6.2676x; 1.1176x over previous
#include <cuda_runtime.h>
#include <math.h>
#include <cstdint>

#define B_ 4
#define S_ 2048
#define D_ 1024
#define H_ 16
#define DK_ 64

// Scratch: device globals (no allocation allowed anywhere)
__device__ float g_Q[(size_t)B_ * S_ * D_];
__device__ float g_K[(size_t)B_ * S_ * D_];
__device__ float g_V[(size_t)B_ * S_ * D_];
__device__ float g_att[(size_t)B_ * S_ * D_];

__device__ __forceinline__ uint32_t f2tf32(float f) {
    uint32_t u;
    asm("cvt.rna.tf32.f32 %0, %1;" : "=r"(u) : "f"(f));
    return u;
}

__device__ __forceinline__ float ex2(float x) {
    float y;
    asm("ex2.approx.ftz.f32 %0, %1;" : "=f"(y) : "f"(x));
    return y;
}

__device__ __forceinline__ void mma_tf32(float* d, const uint32_t* a, const uint32_t* b) {
    asm volatile(
        "mma.sync.aligned.m16n8k8.row.col.f32.tf32.tf32.f32 "
        "{%0,%1,%2,%3}, {%4,%5,%6,%7}, {%8,%9}, {%0,%1,%2,%3};\n"
        : "+f"(d[0]), "+f"(d[1]), "+f"(d[2]), "+f"(d[3])
        : "r"(a[0]), "r"(a[1]), "r"(a[2]), "r"(a[3]), "r"(b[0]), "r"(b[1]));
}

// ---------------------------------------------------------------------------
// GEMM body: C[M,N] = A[M,K] @ B[N,K]^T + bias[N], tf32 mma.sync.
// 128x128x32 CTA tile, 256 threads (8 warps 4x2, warp tile 32x64).
// tf32 conversion happens ONCE per element at staging (LDG->cvt->STS),
// register double-buffered over a single smem buffer.
// ---------------------------------------------------------------------------
__device__ __forceinline__ void gemm_body(
    const float* __restrict__ A, const float* __restrict__ Bm,
    const float* __restrict__ bias, float* __restrict__ C,
    int N, int K, int m0, int n0)
{
    extern __shared__ uint32_t smu[];
    uint32_t* As = smu;              // [128][36]
    uint32_t* Bs = smu + 128 * 36;   // [128][36]

    const int tid = threadIdx.x;
    const int lane = tid & 31, warp = tid >> 5;
    const int wr = warp >> 1, wc = warp & 1;
    const int l4 = lane >> 2, lm = lane & 3;

    const int cr = tid >> 3;          // 0..31
    const int cc = (tid & 7) * 4;     // 0..28

    const float* Ap = A + (size_t)(m0 + cr) * K + cc;
    const float* Bp = Bm + (size_t)(n0 + cr) * K + cc;

    float acc[2][8][4];
#pragma unroll
    for (int i = 0; i < 2; i++)
#pragma unroll
        for (int j = 0; j < 8; j++)
#pragma unroll
            for (int t = 0; t < 4; t++) acc[i][j][t] = 0.f;

    const int nk = K >> 5;

    float4 sa[4], sb[4];
#pragma unroll
    for (int i = 0; i < 4; i++) {
        sa[i] = *(const float4*)(Ap + (size_t)(32 * i) * K);
        sb[i] = *(const float4*)(Bp + (size_t)(32 * i) * K);
    }

    for (int kt = 0; kt < nk; kt++) {
        // store staged tile (convert to tf32 once per element)
#pragma unroll
        for (int i = 0; i < 4; i++) {
            uint4 ua = {f2tf32(sa[i].x), f2tf32(sa[i].y), f2tf32(sa[i].z), f2tf32(sa[i].w)};
            uint4 ub = {f2tf32(sb[i].x), f2tf32(sb[i].y), f2tf32(sb[i].z), f2tf32(sb[i].w)};
            *(uint4*)&As[(cr + 32 * i) * 36 + cc] = ua;
            *(uint4*)&Bs[(cr + 32 * i) * 36 + cc] = ub;
        }
        __syncthreads();

        // prefetch next tile into registers (overlaps with MMA below)
        if (kt + 1 < nk) {
            const int ko = (kt + 1) * 32;
#pragma unroll
            for (int i = 0; i < 4; i++) {
                sa[i] = *(const float4*)(Ap + (size_t)(32 * i) * K + ko);
                sb[i] = *(const float4*)(Bp + (size_t)(32 * i) * K + ko);
            }
        }

#pragma unroll
        for (int ks = 0; ks < 4; ks++) {
            const int kc = ks * 8 + lm;
            uint32_t af[2][4], bf[8][2];
#pragma unroll
            for (int mt = 0; mt < 2; mt++) {
                const int r = wr * 32 + mt * 16 + l4;
                af[mt][0] = As[r * 36 + kc];
                af[mt][1] = As[(r + 8) * 36 + kc];
                af[mt][2] = As[r * 36 + kc + 4];
                af[mt][3] = As[(r + 8) * 36 + kc + 4];
            }
#pragma unroll
            for (int nt = 0; nt < 8; nt++) {
                const int c = wc * 64 + nt * 8 + l4;
                bf[nt][0] = Bs[c * 36 + kc];
                bf[nt][1] = Bs[c * 36 + kc + 4];
            }
#pragma unroll
            for (int mt = 0; mt < 2; mt++)
#pragma unroll
                for (int nt = 0; nt < 8; nt++)
                    mma_tf32(acc[mt][nt], af[mt], bf[nt]);
        }
        __syncthreads();
    }

    // epilogue with bias
#pragma unroll
    for (int mt = 0; mt < 2; mt++) {
        const int r = m0 + wr * 32 + mt * 16 + l4;
#pragma unroll
        for (int nt = 0; nt < 8; nt++) {
            const int c = n0 + wc * 64 + nt * 8 + 2 * lm;
            const float2 b2 = *(const float2*)&bias[c];
            float2 v0 = {acc[mt][nt][0] + b2.x, acc[mt][nt][1] + b2.y};
            float2 v1 = {acc[mt][nt][2] + b2.x, acc[mt][nt][3] + b2.y};
            *(float2*)&C[(size_t)r * N + c] = v0;
            *(float2*)&C[(size_t)(r + 8) * N + c] = v1;
        }
    }
}

// Fused Q/K/V projection: blockIdx.z selects which projection.
__global__ void __launch_bounds__(256) gemm_qkv(
    const float* __restrict__ q, const float* __restrict__ k, const float* __restrict__ v,
    const float* __restrict__ Wq, const float* __restrict__ Wk, const float* __restrict__ Wv,
    const float* __restrict__ bq, const float* __restrict__ bk, const float* __restrict__ bv,
    float* __restrict__ oq, float* __restrict__ ok, float* __restrict__ ov)
{
    const int z = blockIdx.z;
    const float* A = (z == 0) ? q : (z == 1) ? k : v;
    const float* W = (z == 0) ? Wq : (z == 1) ? Wk : Wv;
    const float* bias = (z == 0) ? bq : (z == 1) ? bk : bv;
    float* C = (z == 0) ? oq : (z == 1) ? ok : ov;
    gemm_body(A, W, bias, C, D_, D_, blockIdx.y * 128, blockIdx.x * 128);
}

__global__ void __launch_bounds__(256) gemm_single(
    const float* __restrict__ A, const float* __restrict__ W,
    const float* __restrict__ bias, float* __restrict__ C)
{
    gemm_body(A, W, bias, C, D_, D_, blockIdx.y * 128, blockIdx.x * 128);
}

// ---------------------------------------------------------------------------
// Flash attention, tf32 mma.sync. CTA = 128 q-rows, 256 threads (8 warps x 16
// rows). 64-key tiles. Q fragments live in registers for the whole kernel.
// Softmax runs in log2 domain (scale folds in log2(e)); ex2.approx.
// ---------------------------------------------------------------------------
__global__ void __launch_bounds__(256) attn_tf32(
    const float* __restrict__ Qg, const float* __restrict__ Kg,
    const float* __restrict__ Vg, float* __restrict__ Og)
{
    extern __shared__ float sm[];
    float* QP = sm;                 // [128][68] : Q staging, then P (per-warp rows)
    float* Ks = QP + 128 * 68;      // [64][68]
    float* Vs = Ks + 64 * 68;       // [64][72]

    const int qt = blockIdx.x, h = blockIdx.y, b = blockIdx.z;
    const int tid = threadIdx.x, lane = tid & 31, warp = tid >> 5;
    const int l4 = lane >> 2, lm = lane & 3;
    const int q0 = qt * 128;

    const float* Qb = Qg + (size_t)b * S_ * D_ + h * DK_;
    const float* Kb = Kg + (size_t)b * S_ * D_ + h * DK_;
    const float* Vb = Vg + (size_t)b * S_ * D_ + h * DK_;

    // Load Q tile (convert to tf32 bits)
    {
        const int rr = tid >> 4, c4 = (tid & 15) * 4;
#pragma unroll
        for (int j = 0; j < 8; j++) {
            const int r = rr + j * 16;
            const float4 v = *(const float4*)&Qb[(size_t)(q0 + r) * D_ + c4];
            QP[r * 68 + c4 + 0] = __uint_as_float(f2tf32(v.x));
            QP[r * 68 + c4 + 1] = __uint_as_float(f2tf32(v.y));
            QP[r * 68 + c4 + 2] = __uint_as_float(f2tf32(v.z));
            QP[r * 68 + c4 + 3] = __uint_as_float(f2tf32(v.w));
        }
    }
    __syncthreads();

    // Extract Q fragments (warp reads only its own 16 rows)
    uint32_t qf[8][4];
    {
        const int r = warp * 16 + l4;
#pragma unroll
        for (int ks = 0; ks < 8; ks++) {
            const int c = ks * 8 + lm;
            qf[ks][0] = __float_as_uint(QP[r * 68 + c]);
            qf[ks][1] = __float_as_uint(QP[(r + 8) * 68 + c]);
            qf[ks][2] = __float_as_uint(QP[r * 68 + c + 4]);
            qf[ks][3] = __float_as_uint(QP[(r + 8) * 68 + c + 4]);
        }
    }

    float m0r = -1e30f, m1r = -1e30f, l0r = 0.f, l1r = 0.f;
    float o[8][4];
#pragma unroll
    for (int nt = 0; nt < 8; nt++)
#pragma unroll
        for (int i = 0; i < 4; i++) o[nt][i] = 0.f;

    float* Pw = QP + warp * 16 * 68;
    const int qr_lo = q0 + warp * 16;
    const int qr_hi = qr_lo + 15;
    const int nkb = 2 * qt + 2;

    // scale * log2(e): softmax computed in base-2 domain
    const float SC2 = 0.125f * 1.4426950408889634f;

    for (int kb = 0; kb < nkb; kb++) {
        const int k0 = kb * 64;
        __syncthreads();
        // Cooperative K,V tile load (tf32)
        {
            const int rr = tid >> 4, c4 = (tid & 15) * 4;
#pragma unroll
            for (int j = 0; j < 4; j++) {
                const int r = rr + j * 16;
                const size_t go = (size_t)(k0 + r) * D_ + c4;
                const float4 kv = *(const float4*)&Kb[go];
                const float4 vv = *(const float4*)&Vb[go];
                Ks[r * 68 + c4 + 0] = __uint_as_float(f2tf32(kv.x));
                Ks[r * 68 + c4 + 1] = __uint_as_float(f2tf32(kv.y));
                Ks[r * 68 + c4 + 2] = __uint_as_float(f2tf32(kv.z));
                Ks[r * 68 + c4 + 3] = __uint_as_float(f2tf32(kv.w));
                Vs[r * 72 + c4 + 0] = __uint_as_float(f2tf32(vv.x));
                Vs[r * 72 + c4 + 1] = __uint_as_float(f2tf32(vv.y));
                Vs[r * 72 + c4 + 2] = __uint_as_float(f2tf32(vv.z));
                Vs[r * 72 + c4 + 3] = __uint_as_float(f2tf32(vv.w));
            }
        }
        __syncthreads();
        if (k0 > qr_hi) continue;   // whole tile masked for this warp (uniform)

        // S = Q @ K^T
        float s[8][4];
#pragma unroll
        for (int nt = 0; nt < 8; nt++)
#pragma unroll
            for (int i = 0; i < 4; i++) s[nt][i] = 0.f;
#pragma unroll
        for (int ks = 0; ks < 8; ks++) {
            const int kc = ks * 8 + lm;
#pragma unroll
            for (int nt = 0; nt < 8; nt++) {
                uint32_t bb[2] = {
                    __float_as_uint(Ks[(nt * 8 + l4) * 68 + kc]),
                    __float_as_uint(Ks[(nt * 8 + l4) * 68 + kc + 4])
                };
                mma_tf32(s[nt], qf[ks], bb);
            }
        }

        // scale (log2 domain) + causal mask
        const bool full = (k0 + 63) <= qr_lo;
        const int r0g = qr_lo + l4, r1g = r0g + 8;
#pragma unroll
        for (int nt = 0; nt < 8; nt++) {
#pragma unroll
            for (int i = 0; i < 4; i++) s[nt][i] *= SC2;
            if (!full) {
                const int c = k0 + nt * 8 + 2 * lm;
                if (c     > r0g) s[nt][0] = -1e30f;
                if (c + 1 > r0g) s[nt][1] = -1e30f;
                if (c     > r1g) s[nt][2] = -1e30f;
                if (c + 1 > r1g) s[nt][3] = -1e30f;
            }
        }

        // online softmax (rows r0g: regs 0,1 / r1g: regs 2,3); quad reduction
        float mx0 = -1e30f, mx1 = -1e30f;
#pragma unroll
        for (int nt = 0; nt < 8; nt++) {
            mx0 = fmaxf(mx0, fmaxf(s[nt][0], s[nt][1]));
            mx1 = fmaxf(mx1, fmaxf(s[nt][2], s[nt][3]));
        }
        mx0 = fmaxf(mx0, __shfl_xor_sync(0xffffffffu, mx0, 1));
        mx0 = fmaxf(mx0, __shfl_xor_sync(0xffffffffu, mx0, 2));
        mx1 = fmaxf(mx1, __shfl_xor_sync(0xffffffffu, mx1, 1));
        mx1 = fmaxf(mx1, __shfl_xor_sync(0xffffffffu, mx1, 2));
        const float mn0 = fmaxf(m0r, mx0), mn1 = fmaxf(m1r, mx1);
        const float a0 = ex2(m0r - mn0), a1 = ex2(m1r - mn1);
        m0r = mn0; m1r = mn1;
        float sum0 = 0.f, sum1 = 0.f;
#pragma unroll
        for (int nt = 0; nt < 8; nt++) {
            s[nt][0] = ex2(s[nt][0] - mn0); sum0 += s[nt][0];
            s[nt][1] = ex2(s[nt][1] - mn0); sum0 += s[nt][1];
            s[nt][2] = ex2(s[nt][2] - mn1); sum1 += s[nt][2];
            s[nt][3] = ex2(s[nt][3] - mn1); sum1 += s[nt][3];
        }
        sum0 += __shfl_xor_sync(0xffffffffu, sum0, 1);
        sum0 += __shfl_xor_sync(0xffffffffu, sum0, 2);
        sum1 += __shfl_xor_sync(0xffffffffu, sum1, 1);
        sum1 += __shfl_xor_sync(0xffffffffu, sum1, 2);
        l0r = l0r * a0 + sum0;
        l1r = l1r * a1 + sum1;
#pragma unroll
        for (int nt = 0; nt < 8; nt++) {
            o[nt][0] *= a0; o[nt][1] *= a0;
            o[nt][2] *= a1; o[nt][3] *= a1;
        }

        // store P (tf32) into per-warp region
#pragma unroll
        for (int nt = 0; nt < 8; nt++) {
            const int c = nt * 8 + 2 * lm;
            float2 p0 = {__uint_as_float(f2tf32(s[nt][0])), __uint_as_float(f2tf32(s[nt][1]))};
            float2 p1 = {__uint_as_float(f2tf32(s[nt][2])), __uint_as_float(f2tf32(s[nt][3]))};
            *(float2*)&Pw[l4 * 68 + c]       = p0;
            *(float2*)&Pw[(l4 + 8) * 68 + c] = p1;
        }
        __syncwarp();

        // O += P @ V
#pragma unroll
        for (int ks = 0; ks < 8; ks++) {
            const int kc = ks * 8 + lm;
            uint32_t pa[4];
            pa[0] = __float_as_uint(Pw[l4 * 68 + kc]);
            pa[1] = __float_as_uint(Pw[(l4 + 8) * 68 + kc]);
            pa[2] = __float_as_uint(Pw[l4 * 68 + kc + 4]);
            pa[3] = __float_as_uint(Pw[(l4 + 8) * 68 + kc + 4]);
#pragma unroll
            for (int nt = 0; nt < 8; nt++) {
                uint32_t bb[2] = {
                    __float_as_uint(Vs[(ks * 8 + lm) * 72 + nt * 8 + l4]),
                    __float_as_uint(Vs[(ks * 8 + lm + 4) * 72 + nt * 8 + l4])
                };
                mma_tf32(o[nt], pa, bb);
            }
        }
    }

    // epilogue: normalize and store
    const float inv0 = 1.f / l0r, inv1 = 1.f / l1r;
    float* Ob = Og + (size_t)b * S_ * D_ + h * DK_;
    const int r0g = q0 + warp * 16 + l4, r1g = r0g + 8;
#pragma unroll
    for (int nt = 0; nt < 8; nt++) {
        const int c = nt * 8 + 2 * lm;
        float2 v0 = {o[nt][0] * inv0, o[nt][1] * inv0};
        float2 v1 = {o[nt][2] * inv1, o[nt][3] * inv1};
        *(float2*)&Ob[(size_t)r0g * D_ + c] = v0;
        *(float2*)&Ob[(size_t)r1g * D_ + c] = v1;
    }
}

// ---------------------------------------------------------------------------
extern "C" void kernel_launch(void* const* d_in, const int* in_sizes, int n_in,
                              void* d_out, int out_size)
{
    const float* q  = (const float*)d_in[0];
    const float* k  = (const float*)d_in[1];
    const float* v  = (const float*)d_in[2];
    const float* Wq = (const float*)d_in[3];
    const float* bq = (const float*)d_in[4];
    const float* Wk = (const float*)d_in[5];
    const float* bk = (const float*)d_in[6];
    const float* Wv = (const float*)d_in[7];
    const float* bv = (const float*)d_in[8];
    const float* Wo = (const float*)d_in[9];
    const float* bo = (const float*)d_in[10];
    // d_in[11] = causal mask (computed analytically, unused)
    float* out = (float*)d_out;

    float *pQ, *pK, *pV, *pA;
    cudaGetSymbolAddress((void**)&pQ, g_Q);
    cudaGetSymbolAddress((void**)&pK, g_K);
    cudaGetSymbolAddress((void**)&pV, g_V);
    cudaGetSymbolAddress((void**)&pA, g_att);

    const int M = B_ * S_;  // 8192
    const int gemm_smem = 2 * 128 * 36 * (int)sizeof(uint32_t);   // 36864
    const int attn_smem = (128 * 68 + 64 * 68 + 64 * 72) * (int)sizeof(float);  // 70656

    cudaFuncSetAttribute(gemm_qkv, cudaFuncAttributeMaxDynamicSharedMemorySize, gemm_smem);
    cudaFuncSetAttribute(gemm_single, cudaFuncAttributeMaxDynamicSharedMemorySize, gemm_smem);
    cudaFuncSetAttribute(attn_tf32, cudaFuncAttributeMaxDynamicSharedMemorySize, attn_smem);

    dim3 blk(256);
    dim3 gqkv(D_ / 128, M / 128, 3);  // (8, 64, 3)

    gemm_qkv<<<gqkv, blk, gemm_smem>>>(q, k, v, Wq, Wk, Wv, bq, bk, bv, pQ, pK, pV);

    dim3 gatt(S_ / 128, H_, B_);
    attn_tf32<<<gatt, blk, attn_smem>>>(pQ, pK, pV, pA);

    dim3 gproj(D_ / 128, M / 128);  // (8, 64)
    gemm_single<<<gproj, blk, gemm_smem>>>(pA, Wo, bo, out);
}

// round 4
// speedup vs baseline: 6.5291x; 1.0417x over previous
#include <cuda_runtime.h>
#include <math.h>
#include <cstdint>

#define B_ 4
#define S_ 2048
#define D_ 1024
#define H_ 16
#define DK_ 64

// Scratch: device globals (no allocation allowed anywhere)
__device__ float g_Q[(size_t)B_ * S_ * D_];
__device__ float g_K[(size_t)B_ * S_ * D_];
__device__ float g_V[(size_t)B_ * S_ * D_];
__device__ float g_att[(size_t)B_ * S_ * D_];

__device__ __forceinline__ uint32_t f2tf32(float f) {
    uint32_t u;
    asm("cvt.rna.tf32.f32 %0, %1;" : "=r"(u) : "f"(f));
    return u;
}

__device__ __forceinline__ float ex2(float x) {
    float y;
    asm("ex2.approx.ftz.f32 %0, %1;" : "=f"(y) : "f"(x));
    return y;
}

__device__ __forceinline__ void mma_tf32(float* d, const uint32_t* a, const uint32_t* b) {
    asm volatile(
        "mma.sync.aligned.m16n8k8.row.col.f32.tf32.tf32.f32 "
        "{%0,%1,%2,%3}, {%4,%5,%6,%7}, {%8,%9}, {%0,%1,%2,%3};\n"
        : "+f"(d[0]), "+f"(d[1]), "+f"(d[2]), "+f"(d[3])
        : "r"(a[0]), "r"(a[1]), "r"(a[2]), "r"(a[3]), "r"(b[0]), "r"(b[1]));
}

// ldmatrix x4 (b16 tiles; tf32 data is opaque bits).
// For tf32, one 8x8xb32 tile == two adjacent 8x8xb16 tiles, so x4 loads a full
// m16k8 A-fragment (a0..a3) or two n8k8 B-fragments.
__device__ __forceinline__ void ldsm_x4(uint32_t* r, uint32_t saddr) {
    asm volatile("ldmatrix.sync.aligned.m8n8.x4.shared.b16 {%0,%1,%2,%3}, [%4];"
        : "=r"(r[0]), "=r"(r[1]), "=r"(r[2]), "=r"(r[3]) : "r"(saddr));
}

__device__ __forceinline__ uint32_t s2u(const void* p) {
    return (uint32_t)__cvta_generic_to_shared(p);
}

// ---------------------------------------------------------------------------
// GEMM body: C[M,N] = A[M,K] @ B[N,K]^T + bias[N], tf32 mma.sync.
// 128x128x32 CTA tile, 256 threads (8 warps 4x2, warp tile 32x64).
// tf32 conversion once per element at staging; fragments via ldmatrix.
// ---------------------------------------------------------------------------
__device__ __forceinline__ void gemm_body(
    const float* __restrict__ A, const float* __restrict__ Bm,
    const float* __restrict__ bias, float* __restrict__ C,
    int N, int K, int m0, int n0)
{
    extern __shared__ uint32_t smu[];
    uint32_t* As = smu;              // [128][36]
    uint32_t* Bs = smu + 128 * 36;   // [128][36]

    const int tid = threadIdx.x;
    const int lane = tid & 31, warp = tid >> 5;
    const int wr = warp >> 1, wc = warp & 1;
    const int l4 = lane >> 2, lm = lane & 3;

    const int cr = tid >> 3;          // 0..31
    const int cc = (tid & 7) * 4;     // 0..28

    const float* Ap = A + (size_t)(m0 + cr) * K + cc;
    const float* Bp = Bm + (size_t)(n0 + cr) * K + cc;

    // ldmatrix per-lane base byte offsets
    // A-frag (m16k8): rows = wr*32 [+ mt*16] + (lane&15); +16B col shift for lanes>=16
    const uint32_t a_u = s2u(As) + 4u * ((wr * 32 + (lane & 15)) * 36 + (lane >> 4) * 4);
    // B-frag pair (two n8k8): rows = wc*64 [+ np*16] + (lane&7) + (lane>>4)*8;
    // +16B col shift for lanes 8-15 and 24-31
    const uint32_t b_u = s2u(Bs) + 4u * ((wc * 64 + (lane & 7) + (lane >> 4) * 8) * 36
                                         + ((lane >> 3) & 1) * 4);

    float acc[2][8][4];
#pragma unroll
    for (int i = 0; i < 2; i++)
#pragma unroll
        for (int j = 0; j < 8; j++)
#pragma unroll
            for (int t = 0; t < 4; t++) acc[i][j][t] = 0.f;

    const int nk = K >> 5;

    float4 sa[4], sb[4];
#pragma unroll
    for (int i = 0; i < 4; i++) {
        sa[i] = *(const float4*)(Ap + (size_t)(32 * i) * K);
        sb[i] = *(const float4*)(Bp + (size_t)(32 * i) * K);
    }

    for (int kt = 0; kt < nk; kt++) {
        // store staged tile (convert to tf32 once per element)
#pragma unroll
        for (int i = 0; i < 4; i++) {
            uint4 ua = {f2tf32(sa[i].x), f2tf32(sa[i].y), f2tf32(sa[i].z), f2tf32(sa[i].w)};
            uint4 ub = {f2tf32(sb[i].x), f2tf32(sb[i].y), f2tf32(sb[i].z), f2tf32(sb[i].w)};
            *(uint4*)&As[(cr + 32 * i) * 36 + cc] = ua;
            *(uint4*)&Bs[(cr + 32 * i) * 36 + cc] = ub;
        }
        __syncthreads();

        // prefetch next tile into registers (overlaps with MMA below)
        if (kt + 1 < nk) {
            const int ko = (kt + 1) * 32;
#pragma unroll
            for (int i = 0; i < 4; i++) {
                sa[i] = *(const float4*)(Ap + (size_t)(32 * i) * K + ko);
                sb[i] = *(const float4*)(Bp + (size_t)(32 * i) * K + ko);
            }
        }

#pragma unroll
        for (int ks = 0; ks < 4; ks++) {
            uint32_t af[2][4], bf[4][4];
            ldsm_x4(af[0], a_u + ks * 32);
            ldsm_x4(af[1], a_u + 16 * 36 * 4 + ks * 32);
#pragma unroll
            for (int np = 0; np < 4; np++)
                ldsm_x4(bf[np], b_u + np * (16 * 36 * 4) + ks * 32);
#pragma unroll
            for (int mt = 0; mt < 2; mt++)
#pragma unroll
                for (int np = 0; np < 4; np++) {
                    mma_tf32(acc[mt][2 * np],     af[mt], bf[np]);
                    mma_tf32(acc[mt][2 * np + 1], af[mt], bf[np] + 2);
                }
        }
        __syncthreads();
    }

    // epilogue with bias
#pragma unroll
    for (int mt = 0; mt < 2; mt++) {
        const int r = m0 + wr * 32 + mt * 16 + l4;
#pragma unroll
        for (int nt = 0; nt < 8; nt++) {
            const int c = n0 + wc * 64 + nt * 8 + 2 * lm;
            const float2 b2 = *(const float2*)&bias[c];
            float2 v0 = {acc[mt][nt][0] + b2.x, acc[mt][nt][1] + b2.y};
            float2 v1 = {acc[mt][nt][2] + b2.x, acc[mt][nt][3] + b2.y};
            *(float2*)&C[(size_t)r * N + c] = v0;
            *(float2*)&C[(size_t)(r + 8) * N + c] = v1;
        }
    }
}

// Fused Q/K/V projection: blockIdx.z selects which projection.
__global__ void __launch_bounds__(256) gemm_qkv(
    const float* __restrict__ q, const float* __restrict__ k, const float* __restrict__ v,
    const float* __restrict__ Wq, const float* __restrict__ Wk, const float* __restrict__ Wv,
    const float* __restrict__ bq, const float* __restrict__ bk, const float* __restrict__ bv,
    float* __restrict__ oq, float* __restrict__ ok, float* __restrict__ ov)
{
    const int z = blockIdx.z;
    const float* A = (z == 0) ? q : (z == 1) ? k : v;
    const float* W = (z == 0) ? Wq : (z == 1) ? Wk : Wv;
    const float* bias = (z == 0) ? bq : (z == 1) ? bk : bv;
    float* C = (z == 0) ? oq : (z == 1) ? ok : ov;
    gemm_body(A, W, bias, C, D_, D_, blockIdx.y * 128, blockIdx.x * 128);
}

__global__ void __launch_bounds__(256) gemm_single(
    const float* __restrict__ A, const float* __restrict__ W,
    const float* __restrict__ bias, float* __restrict__ C)
{
    gemm_body(A, W, bias, C, D_, D_, blockIdx.y * 128, blockIdx.x * 128);
}

// ---------------------------------------------------------------------------
// Flash attention, tf32 mma.sync. CTA = 128 q-rows, 256 threads (8 warps x 16
// rows). 64-key tiles. Q fragments register-resident. K and P fragments via
// ldmatrix; V scalar (its b-frag needs a transposed lane map).
// ---------------------------------------------------------------------------
__global__ void __launch_bounds__(256) attn_tf32(
    const float* __restrict__ Qg, const float* __restrict__ Kg,
    const float* __restrict__ Vg, float* __restrict__ Og)
{
    extern __shared__ float sm[];
    float* QP = sm;                 // [128][68] : Q staging, then P (per-warp rows)
    float* Ks = QP + 128 * 68;      // [64][68]
    float* Vs = Ks + 64 * 68;       // [64][72]

    const int qt = blockIdx.x, h = blockIdx.y, b = blockIdx.z;
    const int tid = threadIdx.x, lane = tid & 31, warp = tid >> 5;
    const int l4 = lane >> 2, lm = lane & 3;
    const int q0 = qt * 128;

    const float* Qb = Qg + (size_t)b * S_ * D_ + h * DK_;
    const float* Kb = Kg + (size_t)b * S_ * D_ + h * DK_;
    const float* Vb = Vg + (size_t)b * S_ * D_ + h * DK_;

    // Load Q tile (convert to tf32 bits)
    {
        const int rr = tid >> 4, c4 = (tid & 15) * 4;
#pragma unroll
        for (int j = 0; j < 8; j++) {
            const int r = rr + j * 16;
            const float4 v = *(const float4*)&Qb[(size_t)(q0 + r) * D_ + c4];
            QP[r * 68 + c4 + 0] = __uint_as_float(f2tf32(v.x));
            QP[r * 68 + c4 + 1] = __uint_as_float(f2tf32(v.y));
            QP[r * 68 + c4 + 2] = __uint_as_float(f2tf32(v.z));
            QP[r * 68 + c4 + 3] = __uint_as_float(f2tf32(v.w));
        }
    }
    __syncthreads();

    // Extract Q fragments via ldmatrix (warp reads its own 16 rows)
    uint32_t qf[8][4];
    {
        const uint32_t q_u = s2u(QP) + 4u * ((warp * 16 + (lane & 15)) * 68 + (lane >> 4) * 4);
#pragma unroll
        for (int ks = 0; ks < 8; ks++)
            ldsm_x4(qf[ks], q_u + ks * 32);
    }
    __syncthreads();   // everyone done reading QP before P overwrites it

    // ldmatrix base offsets
    const uint32_t k_u = s2u(Ks) + 4u * (((lane & 7) + (lane >> 4) * 8) * 68
                                         + ((lane >> 3) & 1) * 4);
    const uint32_t p_u = s2u(QP + warp * 16 * 68)
                       + 4u * ((lane & 15) * 68 + (lane >> 4) * 4);

    float m0r = -1e30f, m1r = -1e30f, l0r = 0.f, l1r = 0.f;
    float o[8][4];
#pragma unroll
    for (int nt = 0; nt < 8; nt++)
#pragma unroll
        for (int i = 0; i < 4; i++) o[nt][i] = 0.f;

    float* Pw = QP + warp * 16 * 68;
    const int qr_lo = q0 + warp * 16;
    const int qr_hi = qr_lo + 15;
    const int nkb = 2 * qt + 2;

    // scale * log2(e): softmax computed in base-2 domain
    const float SC2 = 0.125f * 1.4426950408889634f;

    for (int kb = 0; kb < nkb; kb++) {
        const int k0 = kb * 64;
        __syncthreads();
        // Cooperative K,V tile load (tf32)
        {
            const int rr = tid >> 4, c4 = (tid & 15) * 4;
#pragma unroll
            for (int j = 0; j < 4; j++) {
                const int r = rr + j * 16;
                const size_t go = (size_t)(k0 + r) * D_ + c4;
                const float4 kv = *(const float4*)&Kb[go];
                const float4 vv = *(const float4*)&Vb[go];
                Ks[r * 68 + c4 + 0] = __uint_as_float(f2tf32(kv.x));
                Ks[r * 68 + c4 + 1] = __uint_as_float(f2tf32(kv.y));
                Ks[r * 68 + c4 + 2] = __uint_as_float(f2tf32(kv.z));
                Ks[r * 68 + c4 + 3] = __uint_as_float(f2tf32(kv.w));
                Vs[r * 72 + c4 + 0] = __uint_as_float(f2tf32(vv.x));
                Vs[r * 72 + c4 + 1] = __uint_as_float(f2tf32(vv.y));
                Vs[r * 72 + c4 + 2] = __uint_as_float(f2tf32(vv.z));
                Vs[r * 72 + c4 + 3] = __uint_as_float(f2tf32(vv.w));
            }
        }
        __syncthreads();
        if (k0 > qr_hi) continue;   // whole tile masked for this warp (uniform)

        // S = Q @ K^T   (K b-frags via ldmatrix: np pair covers nt=2np,2np+1)
        float s[8][4];
#pragma unroll
        for (int nt = 0; nt < 8; nt++)
#pragma unroll
            for (int i = 0; i < 4; i++) s[nt][i] = 0.f;
#pragma unroll
        for (int ks = 0; ks < 8; ks++) {
#pragma unroll
            for (int np = 0; np < 4; np++) {
                uint32_t bb[4];
                ldsm_x4(bb, k_u + np * (16 * 68 * 4) + ks * 32);
                mma_tf32(s[2 * np],     qf[ks], bb);
                mma_tf32(s[2 * np + 1], qf[ks], bb + 2);
            }
        }

        // scale (log2 domain) + causal mask
        const bool full = (k0 + 63) <= qr_lo;
        const int r0g = qr_lo + l4, r1g = r0g + 8;
#pragma unroll
        for (int nt = 0; nt < 8; nt++) {
#pragma unroll
            for (int i = 0; i < 4; i++) s[nt][i] *= SC2;
            if (!full) {
                const int c = k0 + nt * 8 + 2 * lm;
                if (c     > r0g) s[nt][0] = -1e30f;
                if (c + 1 > r0g) s[nt][1] = -1e30f;
                if (c     > r1g) s[nt][2] = -1e30f;
                if (c + 1 > r1g) s[nt][3] = -1e30f;
            }
        }

        // online softmax (rows r0g: regs 0,1 / r1g: regs 2,3); quad reduction
        float mx0 = -1e30f, mx1 = -1e30f;
#pragma unroll
        for (int nt = 0; nt < 8; nt++) {
            mx0 = fmaxf(mx0, fmaxf(s[nt][0], s[nt][1]));
            mx1 = fmaxf(mx1, fmaxf(s[nt][2], s[nt][3]));
        }
        mx0 = fmaxf(mx0, __shfl_xor_sync(0xffffffffu, mx0, 1));
        mx0 = fmaxf(mx0, __shfl_xor_sync(0xffffffffu, mx0, 2));
        mx1 = fmaxf(mx1, __shfl_xor_sync(0xffffffffu, mx1, 1));
        mx1 = fmaxf(mx1, __shfl_xor_sync(0xffffffffu, mx1, 2));
        const float mn0 = fmaxf(m0r, mx0), mn1 = fmaxf(m1r, mx1);
        const float a0 = ex2(m0r - mn0), a1 = ex2(m1r - mn1);
        m0r = mn0; m1r = mn1;
        float sum0 = 0.f, sum1 = 0.f;
#pragma unroll
        for (int nt = 0; nt < 8; nt++) {
            s[nt][0] = ex2(s[nt][0] - mn0); sum0 += s[nt][0];
            s[nt][1] = ex2(s[nt][1] - mn0); sum0 += s[nt][1];
            s[nt][2] = ex2(s[nt][2] - mn1); sum1 += s[nt][2];
            s[nt][3] = ex2(s[nt][3] - mn1); sum1 += s[nt][3];
        }
        sum0 += __shfl_xor_sync(0xffffffffu, sum0, 1);
        sum0 += __shfl_xor_sync(0xffffffffu, sum0, 2);
        sum1 += __shfl_xor_sync(0xffffffffu, sum1, 1);
        sum1 += __shfl_xor_sync(0xffffffffu, sum1, 2);
        l0r = l0r * a0 + sum0;
        l1r = l1r * a1 + sum1;
#pragma unroll
        for (int nt = 0; nt < 8; nt++) {
            o[nt][0] *= a0; o[nt][1] *= a0;
            o[nt][2] *= a1; o[nt][3] *= a1;
        }

        // store P (tf32) into per-warp region
#pragma unroll
        for (int nt = 0; nt < 8; nt++) {
            const int c = nt * 8 + 2 * lm;
            float2 p0 = {__uint_as_float(f2tf32(s[nt][0])), __uint_as_float(f2tf32(s[nt][1]))};
            float2 p1 = {__uint_as_float(f2tf32(s[nt][2])), __uint_as_float(f2tf32(s[nt][3]))};
            *(float2*)&Pw[l4 * 68 + c]       = p0;
            *(float2*)&Pw[(l4 + 8) * 68 + c] = p1;
        }
        __syncwarp();

        // O += P @ V   (P a-frags via ldmatrix; V scalar)
#pragma unroll
        for (int ks = 0; ks < 8; ks++) {
            uint32_t pa[4];
            ldsm_x4(pa, p_u + ks * 32);
#pragma unroll
            for (int nt = 0; nt < 8; nt++) {
                uint32_t bb[2] = {
                    __float_as_uint(Vs[(ks * 8 + lm) * 72 + nt * 8 + l4]),
                    __float_as_uint(Vs[(ks * 8 + lm + 4) * 72 + nt * 8 + l4])
                };
                mma_tf32(o[nt], pa, bb);
            }
        }
    }

    // epilogue: normalize and store
    const float inv0 = 1.f / l0r, inv1 = 1.f / l1r;
    float* Ob = Og + (size_t)b * S_ * D_ + h * DK_;
    const int r0g = q0 + warp * 16 + l4, r1g = r0g + 8;
#pragma unroll
    for (int nt = 0; nt < 8; nt++) {
        const int c = nt * 8 + 2 * lm;
        float2 v0 = {o[nt][0] * inv0, o[nt][1] * inv0};
        float2 v1 = {o[nt][2] * inv1, o[nt][3] * inv1};
        *(float2*)&Ob[(size_t)r0g * D_ + c] = v0;
        *(float2*)&Ob[(size_t)r1g * D_ + c] = v1;
    }
}

// ---------------------------------------------------------------------------
extern "C" void kernel_launch(void* const* d_in, const int* in_sizes, int n_in,
                              void* d_out, int out_size)
{
    const float* q  = (const float*)d_in[0];
    const float* k  = (const float*)d_in[1];
    const float* v  = (const float*)d_in[2];
    const float* Wq = (const float*)d_in[3];
    const float* bq = (const float*)d_in[4];
    const float* Wk = (const float*)d_in[5];
    const float* bk = (const float*)d_in[6];
    const float* Wv = (const float*)d_in[7];
    const float* bv = (const float*)d_in[8];
    const float* Wo = (const float*)d_in[9];
    const float* bo = (const float*)d_in[10];
    // d_in[11] = causal mask (computed analytically, unused)
    float* out = (float*)d_out;

    float *pQ, *pK, *pV, *pA;
    cudaGetSymbolAddress((void**)&pQ, g_Q);
    cudaGetSymbolAddress((void**)&pK, g_K);
    cudaGetSymbolAddress((void**)&pV, g_V);
    cudaGetSymbolAddress((void**)&pA, g_att);

    const int M = B_ * S_;  // 8192
    const int gemm_smem = 2 * 128 * 36 * (int)sizeof(uint32_t);   // 36864
    const int attn_smem = (128 * 68 + 64 * 68 + 64 * 72) * (int)sizeof(float);  // 70656

    cudaFuncSetAttribute(gemm_qkv, cudaFuncAttributeMaxDynamicSharedMemorySize, gemm_smem);
    cudaFuncSetAttribute(gemm_single, cudaFuncAttributeMaxDynamicSharedMemorySize, gemm_smem);
    cudaFuncSetAttribute(attn_tf32, cudaFuncAttributeMaxDynamicSharedMemorySize, attn_smem);

    dim3 blk(256);
    dim3 gqkv(D_ / 128, M / 128, 3);  // (8, 64, 3)

    gemm_qkv<<<gqkv, blk, gemm_smem>>>(q, k, v, Wq, Wk, Wv, bq, bk, bv, pQ, pK, pV);

    dim3 gatt(S_ / 128, H_, B_);
    attn_tf32<<<gatt, blk, attn_smem>>>(pQ, pK, pV, pA);

    dim3 gproj(D_ / 128, M / 128);  // (8, 64)
    gemm_single<<<gproj, blk, gemm_smem>>>(pA, Wo, bo, out);
}